// round 12
// baseline (speedup 1.0000x reference)
#include <cuda_runtime.h>
#include <math.h>

#define SS        7
#define NPROP     32
#define NCH       128
#define CPB       2               // channels per block
#define FD        32
#define FH        64
#define FW        64
#define CHVOL     (FD * FH * FW)
#define LMAX      18              // max crop extent per dim
#define NROWMAX   (LMAX * LMAX)   // 324
#define THREADS   256
#define RSTRIDE   36              // floor(256/7) row-slots in phase 1
#define NSLOT     5               // floor(256/49) slots in fused pool phase

__global__ __launch_bounds__(THREADS, 8)
void crop_roi_kernel(const float* __restrict__ f,
                     const float* __restrict__ proposals,
                     float* __restrict__ out)
{
    __shared__ float crop7[CPB][NROWMAX * SS];          // 18144 B  x-pooled

    const int n   = blockIdx.x;
    const int cg  = blockIdx.y;                         // c = cg*CPB + {0,1}
    const int tid = threadIdx.x;

    // ---- Geometry (registers only, no barrier needed) ----
    const float* p = proposals + n * 8;
    const int b = (int)p[0];

    int c0[3], L[3];
    const int dims[3] = {FD, FH, FW};
#pragma unroll
    for (int d = 0; d < 3; d++) {
        const float ctr = p[2 + d];
        const float sd  = p[5 + d];
        int lo = (int)floorf((ctr - 0.5f * sd) * 0.25f);
        int hi = (int)ceilf ((ctr + 0.5f * sd) * 0.25f);
        lo = max(lo, 0);
        hi = min(hi, dims[d]);
        c0[d] = lo;
        L[d]  = hi - lo;     // >= 4 (side >= 16)
    }
    const int Lz = L[0], Ly = L[1], Lx = L[2];
    const int nrows = Lz * Ly;                          // <= 324

    // ---- Phase 1: x-pool gmem -> crop7[ch][r*7 + bx], both channels ----
    // Thread layout: tid = r0*7 + bx (x-window constant per thread).
    // Addresses maintained incrementally in registers (no rowoff table, no LDS).
    {
        const int bx = tid % SS;
        const int r0 = tid / SS;                        // 0..36
        const int x0 =  bx      * Lx / SS;
        const int x1 = ((bx + 1) * Lx + SS - 1) / SS;
        const int w  = x1 - x0;                         // 1..4, per-thread constant

        if (r0 < RSTRIDE) {
            // crop-local (z,y) for starting row r0 (one div, once)
            int z = r0 / Ly;
            int y = r0 - z * Ly;
            int off = (z * FH + y) * FW;                // relative to (c0z, c0y, 0)

            const float* fbase = f
                + ((size_t)b * NCH + cg * CPB) * (size_t)CHVOL
                + (c0[0] * FH + c0[1]) * FW + c0[2] + x0;
            const int ZFIX = (FH - Ly) * FW;            // z-rollover adjustment

            for (int r = r0; r < nrows; r += RSTRIDE) {
                const float* rp0 = fbase + off;
                const float* rp1 = rp0 + CHVOL;
                // 8 independent loads in flight per iteration
                float m0 = __ldg(rp0);
                float m1 = __ldg(rp1);
                if (w > 1) { m0 = fmaxf(m0, __ldg(rp0 + 1)); m1 = fmaxf(m1, __ldg(rp1 + 1)); }
                if (w > 2) { m0 = fmaxf(m0, __ldg(rp0 + 2)); m1 = fmaxf(m1, __ldg(rp1 + 2)); }
                if (w > 3) { m0 = fmaxf(m0, __ldg(rp0 + 3)); m1 = fmaxf(m1, __ldg(rp1 + 3)); }
                crop7[0][r * SS + bx] = m0;
                crop7[1][r * SS + bx] = m1;

                // advance by RSTRIDE rows
                off += RSTRIDE * FW;
                y   += RSTRIDE;
                while (y >= Ly) { y -= Ly; off += ZFIX; }
            }
        }
    }
    __syncthreads();

    // ---- Phase 2 (fused y+z pool): crop7 -> out directly ----
    // Thread layout: tid = s0*49 + rem, rem = by*7+bx constant per thread.
    float* outp = out + ((size_t)n * NCH + cg * CPB) * (SS * SS * SS);
    {
        const int rem = tid % (SS * SS);                // by*7+bx, constant
        const int s0  = tid / (SS * SS);                // 0..5
        const int by  = rem / SS;
        const int bx  = rem - by * SS;
        const int y0  =  by      * Ly / SS;
        const int y1  = ((by + 1) * Ly + SS - 1) / SS;
        const int wy  = y1 - y0;                        // 1..4, constant

        if (s0 < NSLOT) {
            // 14 tasks: s = ch*7 + bz
            for (int s = s0; s < CPB * SS; s += NSLOT) {
                const int ch = (s < SS) ? 0 : 1;
                const int bz = (s < SS) ? s : s - SS;
                const int z0 =  bz      * Lz / SS;
                const int z1 = ((bz + 1) * Lz + SS - 1) / SS;

                float m = -INFINITY;
                for (int zz = z0; zz < z1; zz++) {
                    const float* rp = &crop7[ch][(zz * Ly + y0) * SS + bx];
                    float my = rp[0];
                    if (wy > 1) my = fmaxf(my, rp[SS]);
                    if (wy > 2) my = fmaxf(my, rp[2 * SS]);
                    if (wy > 3) my = fmaxf(my, rp[3 * SS]);
                    m = fmaxf(m, my);
                }
                outp[ch * (SS * SS * SS) + bz * (SS * SS) + rem] = m;
            }
        }
    }
}

extern "C" void kernel_launch(void* const* d_in, const int* in_sizes, int n_in,
                              void* d_out, int out_size)
{
    const float* f         = (const float*)d_in[0];
    const float* proposals = (const float*)d_in[2];
    float* out = (float*)d_out;

    dim3 grid(NPROP, NCH / CPB);
    crop_roi_kernel<<<grid, THREADS>>>(f, proposals, out);
}